// round 3
// baseline (speedup 1.0000x reference)
#include <cuda_runtime.h>
#include <cuda_bf16.h>
#include <stdint.h>

#define BB 8
#define NN 4096
#define CC 64
#define QD 8
#define BM 64          // query rows per block (2 warps x 32 rows)
#define BN 64          // key tile rows
#define QT (NN / BM)
#define KT (NN / BN)
#define LDH 72         // sH leading dim (9x16B step -> conflict-free ldsm rows)
#define LOG2E 1.4426950408889634f

// Static device scratch for projections.
__device__ __nv_bfloat16 g_f[BB * NN * QD];   // 0.5 MB
__device__ __nv_bfloat16 g_g[BB * NN * QD];   // 0.5 MB (pre-scaled by log2e)
__device__ __nv_bfloat16 g_h[BB * NN * CC];   // 4 MB

// ---------------------------------------------------------------------------
// PTX helpers
// ---------------------------------------------------------------------------
__device__ __forceinline__ void mma_16n8k8(float* c, const uint32_t* a, uint32_t b)
{
    asm volatile(
        "mma.sync.aligned.m16n8k8.row.col.f32.bf16.bf16.f32 "
        "{%0,%1,%2,%3}, {%4,%5}, {%6}, {%0,%1,%2,%3};\n"
        : "+f"(c[0]), "+f"(c[1]), "+f"(c[2]), "+f"(c[3])
        : "r"(a[0]), "r"(a[1]), "r"(b));
}

__device__ __forceinline__ void mma_16n8k16(float* c, const uint32_t* a, const uint32_t* b)
{
    asm volatile(
        "mma.sync.aligned.m16n8k16.row.col.f32.bf16.bf16.f32 "
        "{%0,%1,%2,%3}, {%4,%5,%6,%7}, {%8,%9}, {%0,%1,%2,%3};\n"
        : "+f"(c[0]), "+f"(c[1]), "+f"(c[2]), "+f"(c[3])
        : "r"(a[0]), "r"(a[1]), "r"(a[2]), "r"(a[3]), "r"(b[0]), "r"(b[1]));
}

__device__ __forceinline__ void ldsm_x4(uint32_t* r, const void* smem_ptr)
{
    uint32_t addr = (uint32_t)__cvta_generic_to_shared(smem_ptr);
    asm volatile(
        "ldmatrix.sync.aligned.m8n8.x4.shared.b16 {%0,%1,%2,%3}, [%4];\n"
        : "=r"(r[0]), "=r"(r[1]), "=r"(r[2]), "=r"(r[3]) : "r"(addr));
}

__device__ __forceinline__ void ldsm_x4_trans(uint32_t* r, const void* smem_ptr)
{
    uint32_t addr = (uint32_t)__cvta_generic_to_shared(smem_ptr);
    asm volatile(
        "ldmatrix.sync.aligned.m8n8.x4.trans.shared.b16 {%0,%1,%2,%3}, [%4];\n"
        : "=r"(r[0]), "=r"(r[1]), "=r"(r[2]), "=r"(r[3]) : "r"(addr));
}

__device__ __forceinline__ uint32_t pack_bf162(float a, float b)
{
    __nv_bfloat162 t = __floats2bfloat162_rn(a, b);
    return *(uint32_t*)&t;
}

__device__ __forceinline__ float ex2f(float x)
{
    float y;
    asm("ex2.approx.f32 %0, %1;\n" : "=f"(y) : "f"(x));
    return y;
}

__device__ __forceinline__ void cp_async16(void* smem_dst, const void* gmem_src)
{
    uint32_t d = (uint32_t)__cvta_generic_to_shared(smem_dst);
    asm volatile("cp.async.cg.shared.global [%0], [%1], 16;\n"
                 :: "r"(d), "l"(gmem_src) : "memory");
}
__device__ __forceinline__ void cp_async_commit()
{
    asm volatile("cp.async.commit_group;\n" ::: "memory");
}
__device__ __forceinline__ void cp_async_wait0()
{
    asm volatile("cp.async.wait_group 0;\n" ::: "memory");
}

// ---------------------------------------------------------------------------
// Kernel 1: projections as HMMA GEMM.  [64 rows x 64] @ [64 x 80] per block.
// 512 blocks x 128 threads (4 warps, 16 rows each). Wg pre-scaled by log2e.
// ---------------------------------------------------------------------------
#define LDW 88
#define LDX 72
__global__ __launch_bounds__(128) void proj_kernel(
    const float* __restrict__ x,
    const float* __restrict__ kf,
    const float* __restrict__ kg,
    const float* __restrict__ kh)
{
    __shared__ __nv_bfloat16 sW[64 * LDW];   // row c: d 0-7 f, 8-15 g(scaled), 16-79 h
    __shared__ __nv_bfloat16 sX[64 * LDX];

    int tid  = threadIdx.x;
    int lane = tid & 31;
    int w    = tid >> 5;
    int gid  = lane >> 2;
    int tg   = lane & 3;

    for (int idx = tid; idx < 64 * 80; idx += 128) {
        int c = idx / 80, d = idx % 80;
        float v;
        if (d < 8)       v = kf[c * 8 + d];
        else if (d < 16) v = kg[c * 8 + (d - 8)] * LOG2E;
        else             v = kh[c * 64 + (d - 16)];
        sW[c * LDW + d] = __float2bfloat16(v);
    }
    long base = (long)blockIdx.x * 64;
    const float4* xg = (const float4*)(x + base * 64);
    for (int i = tid; i < 1024; i += 128) {
        int r = i >> 4, c4 = (i & 15) * 4;
        float4 v = xg[i];
        __nv_bfloat162* dst = (__nv_bfloat162*)&sX[r * LDX + c4];
        dst[0] = __floats2bfloat162_rn(v.x, v.y);
        dst[1] = __floats2bfloat162_rn(v.z, v.w);
    }
    __syncthreads();

    float c[10][4];
#pragma unroll
    for (int n = 0; n < 10; n++)
#pragma unroll
        for (int i = 0; i < 4; i++) c[n][i] = 0.f;

#pragma unroll
    for (int kk = 0; kk < 4; kk++) {
        uint32_t a[4];
        ldsm_x4(a, &sX[(w * 16 + (lane & 15)) * LDX + kk * 16 + (lane >> 4) * 8]);
#pragma unroll
        for (int np = 0; np < 5; np++) {
            uint32_t bfr[4];
            ldsm_x4_trans(bfr,
                &sW[(kk * 16 + (lane & 15)) * LDW + np * 16 + (lane >> 4) * 8]);
            mma_16n8k16(c[2 * np],     a, &bfr[0]);
            mma_16n8k16(c[2 * np + 1], a, &bfr[2]);
        }
    }

    // Fragment-direct scattered stores: d = 16*np + 8*h + 2*tg (static routing).
    long r0 = base + w * 16 + gid;
    long r1 = r0 + 8;
#pragma unroll
    for (int np = 0; np < 5; np++) {
#pragma unroll
        for (int h = 0; h < 2; h++) {
            int dbase = 16 * np + 8 * h;
            uint32_t u0 = pack_bf162(c[2 * np + h][0], c[2 * np + h][1]);
            uint32_t u1 = pack_bf162(c[2 * np + h][2], c[2 * np + h][3]);
            if (dbase == 0) {
                *(uint32_t*)&g_f[r0 * QD + 2 * tg] = u0;
                *(uint32_t*)&g_f[r1 * QD + 2 * tg] = u1;
            } else if (dbase == 8) {
                *(uint32_t*)&g_g[r0 * QD + 2 * tg] = u0;
                *(uint32_t*)&g_g[r1 * QD + 2 * tg] = u1;
            } else {
                int d = dbase - 16 + 2 * tg;
                *(uint32_t*)&g_h[r0 * CC + d] = u0;
                *(uint32_t*)&g_h[r1 * CC + d] = u1;
            }
        }
    }
}

// ---------------------------------------------------------------------------
// Kernel 2: flash attention. 64-thread blocks (2 warps), warp owns 32 rows
// as two m16 chunks sharing every H B-fragment (halves smem traffic/row).
// cp.async double-buffered key tiles; exp is a bare ex2 (log2e pre-folded).
// ---------------------------------------------------------------------------
__global__ __launch_bounds__(64) void attn_kernel(
    const float* __restrict__ x,
    const float* __restrict__ gamma_p,
    float* __restrict__ out)
{
    __shared__ __nv_bfloat16 sG[BM * QD];          // 1 KB
    __shared__ __nv_bfloat16 sF[2][BN * QD];       // 2 KB
    __shared__ __nv_bfloat16 sH[2][BN * LDH];      // 18 KB

    int tid  = threadIdx.x;
    int lane = tid & 31;
    int w    = tid >> 5;          // 0..1
    int gid  = lane >> 2;
    int tg   = lane & 3;
    int b    = blockIdx.x / QT;
    int qt   = blockIdx.x % QT;
    long qbase = (long)b * NN + (long)qt * BM;
    long kb0   = (long)b * NN;

    float gmm = gamma_p[0];

    // Prologue: async-load G tile + key tile 0.
    cp_async16(&sG[tid * 8], &g_g[(qbase + tid) * QD]);
    cp_async16(&sF[0][tid * 8], &g_f[(kb0 + tid) * QD]);
#pragma unroll
    for (int i = 0; i < 8; i++) {
        int idx = tid + 64 * i;                   // 0..511 (uint4 units)
        cp_async16(&sH[0][(idx >> 3) * LDH + (idx & 7) * 8],
                   &g_h[kb0 * CC + idx * 8]);
    }
    cp_async_commit();
    cp_async_wait0();
    __syncthreads();

    // A fragments of G for the two m16 chunks (rows w*32 + {gid, gid+8, gid+16, gid+24}).
    uint32_t ga0[2], ga1[2];
    ga0[0] = *(const uint32_t*)&sG[(w * 32 + gid)      * QD + 2 * tg];
    ga0[1] = *(const uint32_t*)&sG[(w * 32 + gid + 8)  * QD + 2 * tg];
    ga1[0] = *(const uint32_t*)&sG[(w * 32 + gid + 16) * QD + 2 * tg];
    ga1[1] = *(const uint32_t*)&sG[(w * 32 + gid + 24) * QD + 2 * tg];

    float o0[8][4], o1[8][4];
#pragma unroll
    for (int n = 0; n < 8; n++)
#pragma unroll
        for (int i = 0; i < 4; i++) { o0[n][i] = 0.f; o1[n][i] = 0.f; }
    float l0 = 0.f, l1 = 0.f, l2 = 0.f, l3 = 0.f;

    for (int kt = 0; kt < KT; kt++) {
        int p = kt & 1;

        // Issue next tile's async copies into the other buffer.
        if (kt + 1 < KT) {
            long kb = kb0 + (long)(kt + 1) * BN;
            cp_async16(&sF[p ^ 1][tid * 8], &g_f[(kb + tid) * QD]);
#pragma unroll
            for (int i = 0; i < 8; i++) {
                int idx = tid + 64 * i;
                cp_async16(&sH[p ^ 1][(idx >> 3) * LDH + (idx & 7) * 8],
                           &g_h[kb * CC + idx * 8]);
            }
            cp_async_commit();
        }

        // F B-fragments (single LDS.32 each), shared by both m-chunks.
        uint32_t fb[8];
#pragma unroll
        for (int j = 0; j < 8; j++)
            fb[j] = *(const uint32_t*)&sF[p][(j * 8 + gid) * QD + 2 * tg];

        // S = G @ F^T, exp in registers (ex2: log2e folded into g), pack bf16.
        uint32_t pa0[8], pb0[8], pa1[8], pb1[8];
#pragma unroll
        for (int j = 0; j < 8; j++) {
            float s[4] = {0.f, 0.f, 0.f, 0.f};
            mma_16n8k8(s, ga0, fb[j]);
            float e0 = ex2f(s[0]), e1 = ex2f(s[1]);
            float e2 = ex2f(s[2]), e3 = ex2f(s[3]);
            l0 += e0 + e1; l1 += e2 + e3;
            pa0[j] = pack_bf162(e0, e1);
            pb0[j] = pack_bf162(e2, e3);
        }
#pragma unroll
        for (int j = 0; j < 8; j++) {
            float s[4] = {0.f, 0.f, 0.f, 0.f};
            mma_16n8k8(s, ga1, fb[j]);
            float e0 = ex2f(s[0]), e1 = ex2f(s[1]);
            float e2 = ex2f(s[2]), e3 = ex2f(s[3]);
            l2 += e0 + e1; l3 += e2 + e3;
            pa1[j] = pack_bf162(e0, e1);
            pb1[j] = pack_bf162(e2, e3);
        }

        // O += P @ H; every H B-fragment feeds both m-chunks.
#pragma unroll
        for (int kk = 0; kk < 4; kk++) {
            uint32_t a0[4] = { pa0[2 * kk], pb0[2 * kk], pa0[2 * kk + 1], pb0[2 * kk + 1] };
            uint32_t a1[4] = { pa1[2 * kk], pb1[2 * kk], pa1[2 * kk + 1], pb1[2 * kk + 1] };
#pragma unroll
            for (int np = 0; np < 4; np++) {
                uint32_t bfr[4];
                ldsm_x4_trans(bfr,
                    &sH[p][(kk * 16 + (lane & 15)) * LDH + np * 16 + (lane >> 4) * 8]);
                mma_16n8k16(o0[2 * np],     a0, &bfr[0]);
                mma_16n8k16(o0[2 * np + 1], a0, &bfr[2]);
                mma_16n8k16(o1[2 * np],     a1, &bfr[0]);
                mma_16n8k16(o1[2 * np + 1], a1, &bfr[2]);
            }
        }

        if (kt + 1 < KT) {
            cp_async_wait0();
            __syncthreads();
        }
    }

    // Reduce row-sums across the 4 lanes of each row group.
    l0 += __shfl_xor_sync(0xffffffffu, l0, 1); l0 += __shfl_xor_sync(0xffffffffu, l0, 2);
    l1 += __shfl_xor_sync(0xffffffffu, l1, 1); l1 += __shfl_xor_sync(0xffffffffu, l1, 2);
    l2 += __shfl_xor_sync(0xffffffffu, l2, 1); l2 += __shfl_xor_sync(0xffffffffu, l2, 2);
    l3 += __shfl_xor_sync(0xffffffffu, l3, 1); l3 += __shfl_xor_sync(0xffffffffu, l3, 2);
    float inv0 = gmm / l0, inv1 = gmm / l1, inv2 = gmm / l2, inv3 = gmm / l3;

    long r0 = qbase + w * 32 + gid;
#pragma unroll
    for (int n = 0; n < 8; n++) {
        int col = n * 8 + 2 * tg;
        float2 x0 = *(const float2*)&x[(r0)      * CC + col];
        float2 x1 = *(const float2*)&x[(r0 + 8)  * CC + col];
        float2 x2 = *(const float2*)&x[(r0 + 16) * CC + col];
        float2 x3 = *(const float2*)&x[(r0 + 24) * CC + col];
        float2 v;
        v.x = o0[n][0] * inv0 + x0.x; v.y = o0[n][1] * inv0 + x0.y;
        *(float2*)&out[(r0)      * CC + col] = v;
        v.x = o0[n][2] * inv1 + x1.x; v.y = o0[n][3] * inv1 + x1.y;
        *(float2*)&out[(r0 + 8)  * CC + col] = v;
        v.x = o1[n][0] * inv2 + x2.x; v.y = o1[n][1] * inv2 + x2.y;
        *(float2*)&out[(r0 + 16) * CC + col] = v;
        v.x = o1[n][2] * inv3 + x3.x; v.y = o1[n][3] * inv3 + x3.y;
        *(float2*)&out[(r0 + 24) * CC + col] = v;
    }
}

// ---------------------------------------------------------------------------

extern "C" void kernel_launch(void* const* d_in, const int* in_sizes, int n_in,
                              void* d_out, int out_size)
{
    const float* x     = (const float*)d_in[0];
    const float* kf    = (const float*)d_in[1];
    const float* kg    = (const float*)d_in[2];
    const float* kh    = (const float*)d_in[3];
    const float* gamma = (const float*)d_in[4];
    float*       out   = (float*)d_out;

    proj_kernel<<<(BB * NN) / 64, 128>>>(x, kf, kg, kh);
    attn_kernel<<<BB * QT, 64>>>(x, gamma, out);
}

// round 4
// speedup vs baseline: 1.6854x; 1.6854x over previous
#include <cuda_runtime.h>
#include <cuda_bf16.h>
#include <stdint.h>

#define BB 8
#define NN 4096
#define CC 64
#define QD 8
#define BM 64          // query rows per block
#define BN 64          // key tile rows
#define QT (NN / BM)
#define KT (NN / BN)
#define LDH 72         // sH leading dim
#define LDO 72         // epilogue O overlay leading dim (floats)
#define LOG2E 1.4426950408889634f

// Static device scratch for projections.
__device__ __nv_bfloat16 g_f[BB * NN * QD];   // 0.5 MB
__device__ __nv_bfloat16 g_g[BB * NN * QD];   // 0.5 MB (pre-scaled by log2e)
__device__ __nv_bfloat16 g_h[BB * NN * CC];   // 4 MB

// ---------------------------------------------------------------------------
// PTX helpers
// ---------------------------------------------------------------------------
__device__ __forceinline__ void mma_16n8k8(float* c, const uint32_t* a, uint32_t b)
{
    asm volatile(
        "mma.sync.aligned.m16n8k8.row.col.f32.bf16.bf16.f32 "
        "{%0,%1,%2,%3}, {%4,%5}, {%6}, {%0,%1,%2,%3};\n"
        : "+f"(c[0]), "+f"(c[1]), "+f"(c[2]), "+f"(c[3])
        : "r"(a[0]), "r"(a[1]), "r"(b));
}

__device__ __forceinline__ void mma_16n8k16(float* c, const uint32_t* a, const uint32_t* b)
{
    asm volatile(
        "mma.sync.aligned.m16n8k16.row.col.f32.bf16.bf16.f32 "
        "{%0,%1,%2,%3}, {%4,%5,%6,%7}, {%8,%9}, {%0,%1,%2,%3};\n"
        : "+f"(c[0]), "+f"(c[1]), "+f"(c[2]), "+f"(c[3])
        : "r"(a[0]), "r"(a[1]), "r"(a[2]), "r"(a[3]), "r"(b[0]), "r"(b[1]));
}

__device__ __forceinline__ void ldsm_x4(uint32_t* r, const void* smem_ptr)
{
    uint32_t addr = (uint32_t)__cvta_generic_to_shared(smem_ptr);
    asm volatile(
        "ldmatrix.sync.aligned.m8n8.x4.shared.b16 {%0,%1,%2,%3}, [%4];\n"
        : "=r"(r[0]), "=r"(r[1]), "=r"(r[2]), "=r"(r[3]) : "r"(addr));
}

__device__ __forceinline__ void ldsm_x4_trans(uint32_t* r, const void* smem_ptr)
{
    uint32_t addr = (uint32_t)__cvta_generic_to_shared(smem_ptr);
    asm volatile(
        "ldmatrix.sync.aligned.m8n8.x4.trans.shared.b16 {%0,%1,%2,%3}, [%4];\n"
        : "=r"(r[0]), "=r"(r[1]), "=r"(r[2]), "=r"(r[3]) : "r"(addr));
}

__device__ __forceinline__ uint32_t pack_bf162(float a, float b)
{
    __nv_bfloat162 t = __floats2bfloat162_rn(a, b);
    return *(uint32_t*)&t;
}

__device__ __forceinline__ float ex2f(float x)
{
    float y;
    asm("ex2.approx.f32 %0, %1;\n" : "=f"(y) : "f"(x));
    return y;
}

__device__ __forceinline__ void cp_async16(void* smem_dst, const void* gmem_src)
{
    uint32_t d = (uint32_t)__cvta_generic_to_shared(smem_dst);
    asm volatile("cp.async.cg.shared.global [%0], [%1], 16;\n"
                 :: "r"(d), "l"(gmem_src) : "memory");
}
__device__ __forceinline__ void cp_async_commit()
{
    asm volatile("cp.async.commit_group;\n" ::: "memory");
}
__device__ __forceinline__ void cp_async_wait0()
{
    asm volatile("cp.async.wait_group 0;\n" ::: "memory");
}

// ---------------------------------------------------------------------------
// Kernel 1: projections as HMMA GEMM.  [128 rows x 64] @ [64 x 80] per block.
// 256 blocks x 256 threads (8 warps, 16 rows each). Wg pre-scaled by log2e.
// ---------------------------------------------------------------------------
#define LDW 88
#define LDX 72
__global__ __launch_bounds__(256) void proj_kernel(
    const float* __restrict__ x,
    const float* __restrict__ kf,
    const float* __restrict__ kg,
    const float* __restrict__ kh)
{
    __shared__ __nv_bfloat16 sW[64 * LDW];    // row c: d 0-7 f, 8-15 g(scaled), 16-79 h
    __shared__ __nv_bfloat16 sX[128 * LDX];

    int tid  = threadIdx.x;
    int lane = tid & 31;
    int w    = tid >> 5;
    int gid  = lane >> 2;
    int tg   = lane & 3;

    for (int idx = tid; idx < 64 * 80; idx += 256) {
        int c = idx / 80, d = idx % 80;
        float v;
        if (d < 8)       v = kf[c * 8 + d];
        else if (d < 16) v = kg[c * 8 + (d - 8)] * LOG2E;
        else             v = kh[c * 64 + (d - 16)];
        sW[c * LDW + d] = __float2bfloat16(v);
    }
    long base = (long)blockIdx.x * 128;
    const float4* xg = (const float4*)(x + base * 64);
    for (int i = tid; i < 2048; i += 256) {
        int r = i >> 4, c4 = (i & 15) * 4;
        float4 v = xg[i];
        __nv_bfloat162* dst = (__nv_bfloat162*)&sX[r * LDX + c4];
        dst[0] = __floats2bfloat162_rn(v.x, v.y);
        dst[1] = __floats2bfloat162_rn(v.z, v.w);
    }
    __syncthreads();

    float c[10][4];
#pragma unroll
    for (int n = 0; n < 10; n++)
#pragma unroll
        for (int i = 0; i < 4; i++) c[n][i] = 0.f;

#pragma unroll
    for (int kk = 0; kk < 4; kk++) {
        uint32_t a[4];
        ldsm_x4(a, &sX[(w * 16 + (lane & 15)) * LDX + kk * 16 + (lane >> 4) * 8]);
#pragma unroll
        for (int np = 0; np < 5; np++) {
            uint32_t bfr[4];
            ldsm_x4_trans(bfr,
                &sW[(kk * 16 + (lane & 15)) * LDW + np * 16 + (lane >> 4) * 8]);
            mma_16n8k16(c[2 * np],     a, &bfr[0]);
            mma_16n8k16(c[2 * np + 1], a, &bfr[2]);
        }
    }

    // Fragment-direct scattered stores: d = 16*np + 8*h + 2*tg (static routing).
    long r0 = base + w * 16 + gid;
    long r1 = r0 + 8;
#pragma unroll
    for (int np = 0; np < 5; np++) {
#pragma unroll
        for (int h = 0; h < 2; h++) {
            int dbase = 16 * np + 8 * h;
            uint32_t u0 = pack_bf162(c[2 * np + h][0], c[2 * np + h][1]);
            uint32_t u1 = pack_bf162(c[2 * np + h][2], c[2 * np + h][3]);
            if (dbase == 0) {
                *(uint32_t*)&g_f[r0 * QD + 2 * tg] = u0;
                *(uint32_t*)&g_f[r1 * QD + 2 * tg] = u1;
            } else if (dbase == 8) {
                *(uint32_t*)&g_g[r0 * QD + 2 * tg] = u0;
                *(uint32_t*)&g_g[r1 * QD + 2 * tg] = u1;
            } else {
                int d = dbase - 16 + 2 * tg;
                *(uint32_t*)&g_h[r0 * CC + d] = u0;
                *(uint32_t*)&g_h[r1 * CC + d] = u1;
            }
        }
    }
}

// ---------------------------------------------------------------------------
// Kernel 2: flash attention. 128 threads = 2 warp-pairs.
// Pair p (warps 2p, 2p+1) processes key tiles kt = p, p+2, ... with its own
// double buffer + named barrier. Each warp owns all 64 rows' worth: warp-in-
// pair wp covers rows [wp*32, wp*32+32) as two m16 chunks sharing every H
// B-fragment. Partial O / rowsums joined through smem at the end.
// ---------------------------------------------------------------------------
__global__ __launch_bounds__(128) void attn_kernel(
    const float* __restrict__ x,
    const float* __restrict__ gamma_p,
    float* __restrict__ out)
{
    __shared__ __nv_bfloat16 sG[BM * QD];             // 1 KB
    __shared__ __nv_bfloat16 sF[2][2][BN * QD];       // 4 KB   [pair][buf]
    __shared__ __nv_bfloat16 sH[2][2][BN * LDH];      // 36 KB  [pair][buf]
    __shared__ float         sL[BM];

    int tid  = threadIdx.x;
    int lane = tid & 31;
    int w    = tid >> 5;          // 0..3
    int pair = w >> 1;            // 0..1: key-tile parity this warp handles
    int wp   = w & 1;             // warp-in-pair: row half
    int pt   = tid & 63;          // pair-local thread id
    int gid  = lane >> 2;
    int tg   = lane & 3;
    int b    = blockIdx.x / QT;
    int qt   = blockIdx.x % QT;
    long qbase = (long)b * NN + (long)qt * BM;
    long kb0   = (long)b * NN;

    float gmm = gamma_p[0];

    // Prologue: G tile + each pair's first key tile (kt = pair).
    if (tid < 64) cp_async16(&sG[tid * 8], &g_g[(qbase + tid) * QD]);
    {
        long kb = kb0 + (long)pair * BN;
        cp_async16(&sF[pair][0][pt * 8], &g_f[(kb + pt) * QD]);
#pragma unroll
        for (int i = 0; i < 8; i++) {
            int idx = pt + 64 * i;
            cp_async16(&sH[pair][0][(idx >> 3) * LDH + (idx & 7) * 8],
                       &g_h[kb * CC + idx * 8]);
        }
    }
    cp_async_commit();
    cp_async_wait0();
    __syncthreads();

    // G A-fragments for rows wp*32 + {gid, gid+8, gid+16, gid+24}.
    uint32_t ga0[2], ga1[2];
    ga0[0] = *(const uint32_t*)&sG[(wp * 32 + gid)      * QD + 2 * tg];
    ga0[1] = *(const uint32_t*)&sG[(wp * 32 + gid + 8)  * QD + 2 * tg];
    ga1[0] = *(const uint32_t*)&sG[(wp * 32 + gid + 16) * QD + 2 * tg];
    ga1[1] = *(const uint32_t*)&sG[(wp * 32 + gid + 24) * QD + 2 * tg];

    float o0[8][4], o1[8][4];
#pragma unroll
    for (int n = 0; n < 8; n++)
#pragma unroll
        for (int i = 0; i < 4; i++) { o0[n][i] = 0.f; o1[n][i] = 0.f; }
    float l0 = 0.f, l1 = 0.f, l2 = 0.f, l3 = 0.f;

    const int NI = KT / 2;   // 32 iterations per pair
    for (int i = 0; i < NI; i++) {
        int buf = i & 1;

        // Prefetch this pair's next key tile (kt = 2*(i+1)+pair).
        if (i + 1 < NI) {
            long kb = kb0 + (long)(2 * (i + 1) + pair) * BN;
            cp_async16(&sF[pair][buf ^ 1][pt * 8], &g_f[(kb + pt) * QD]);
#pragma unroll
            for (int j = 0; j < 8; j++) {
                int idx = pt + 64 * j;
                cp_async16(&sH[pair][buf ^ 1][(idx >> 3) * LDH + (idx & 7) * 8],
                           &g_h[kb * CC + idx * 8]);
            }
            cp_async_commit();
        }

        // F B-fragments (single LDS.32 each), shared by both m-chunks.
        uint32_t fb[8];
#pragma unroll
        for (int j = 0; j < 8; j++)
            fb[j] = *(const uint32_t*)&sF[pair][buf][(j * 8 + gid) * QD + 2 * tg];

        // S = G @ F^T, exp in registers (ex2: log2e folded into g), pack bf16.
        uint32_t pa0[8], pb0[8], pa1[8], pb1[8];
#pragma unroll
        for (int j = 0; j < 8; j++) {
            float s[4] = {0.f, 0.f, 0.f, 0.f};
            mma_16n8k8(s, ga0, fb[j]);
            float e0 = ex2f(s[0]), e1 = ex2f(s[1]);
            float e2 = ex2f(s[2]), e3 = ex2f(s[3]);
            l0 += e0 + e1; l1 += e2 + e3;
            pa0[j] = pack_bf162(e0, e1);
            pb0[j] = pack_bf162(e2, e3);
        }
#pragma unroll
        for (int j = 0; j < 8; j++) {
            float s[4] = {0.f, 0.f, 0.f, 0.f};
            mma_16n8k8(s, ga1, fb[j]);
            float e0 = ex2f(s[0]), e1 = ex2f(s[1]);
            float e2 = ex2f(s[2]), e3 = ex2f(s[3]);
            l2 += e0 + e1; l3 += e2 + e3;
            pa1[j] = pack_bf162(e0, e1);
            pb1[j] = pack_bf162(e2, e3);
        }

        // O += P @ H; every H B-fragment feeds both m-chunks.
#pragma unroll
        for (int kk = 0; kk < 4; kk++) {
            uint32_t a0[4] = { pa0[2 * kk], pb0[2 * kk], pa0[2 * kk + 1], pb0[2 * kk + 1] };
            uint32_t a1[4] = { pa1[2 * kk], pb1[2 * kk], pa1[2 * kk + 1], pb1[2 * kk + 1] };
#pragma unroll
            for (int np = 0; np < 4; np++) {
                uint32_t bfr[4];
                ldsm_x4_trans(bfr,
                    &sH[pair][buf][(kk * 16 + (lane & 15)) * LDH + np * 16 + (lane >> 4) * 8]);
                mma_16n8k16(o0[2 * np],     a0, &bfr[0]);
                mma_16n8k16(o0[2 * np + 1], a0, &bfr[2]);
                mma_16n8k16(o1[2 * np],     a1, &bfr[0]);
                mma_16n8k16(o1[2 * np + 1], a1, &bfr[2]);
            }
        }

        if (i + 1 < NI) {
            cp_async_wait0();
            // Pair-local barrier (64 threads): ids 1 and 2.
            asm volatile("bar.sync %0, 64;\n" :: "r"(1 + pair) : "memory");
        }
    }

    // Reduce rowsums across the 4 lanes of each row group.
    l0 += __shfl_xor_sync(0xffffffffu, l0, 1); l0 += __shfl_xor_sync(0xffffffffu, l0, 2);
    l1 += __shfl_xor_sync(0xffffffffu, l1, 1); l1 += __shfl_xor_sync(0xffffffffu, l1, 2);
    l2 += __shfl_xor_sync(0xffffffffu, l2, 1); l2 += __shfl_xor_sync(0xffffffffu, l2, 2);
    l3 += __shfl_xor_sync(0xffffffffu, l3, 1); l3 += __shfl_xor_sync(0xffffffffu, l3, 2);

    // Join the two pairs: pair 1 parks its partial O + l in smem (overlaying
    // the now-dead sH buffers), pair 0 combines and writes out.
    __syncthreads();
    float* sO = (float*)&sH[0][0][0];   // 64 x LDO floats = 18.4 KB (< 36 KB)
    int r0 = wp * 32 + gid;
    if (pair == 1) {
#pragma unroll
        for (int n = 0; n < 8; n++) {
            int col = n * 8 + 2 * tg;
            *(float2*)&sO[(r0)      * LDO + col] = make_float2(o0[n][0], o0[n][1]);
            *(float2*)&sO[(r0 + 8)  * LDO + col] = make_float2(o0[n][2], o0[n][3]);
            *(float2*)&sO[(r0 + 16) * LDO + col] = make_float2(o1[n][0], o1[n][1]);
            *(float2*)&sO[(r0 + 24) * LDO + col] = make_float2(o1[n][2], o1[n][3]);
        }
        if (tg == 0) {
            sL[r0] = l0; sL[r0 + 8] = l1; sL[r0 + 16] = l2; sL[r0 + 24] = l3;
        }
    }
    __syncthreads();
    if (pair == 0) {
        float inv0 = gmm / (l0 + sL[r0]);
        float inv1 = gmm / (l1 + sL[r0 + 8]);
        float inv2 = gmm / (l2 + sL[r0 + 16]);
        float inv3 = gmm / (l3 + sL[r0 + 24]);
        long rg = qbase + r0;
#pragma unroll
        for (int n = 0; n < 8; n++) {
            int col = n * 8 + 2 * tg;
            float2 p0 = *(const float2*)&sO[(r0)      * LDO + col];
            float2 p1 = *(const float2*)&sO[(r0 + 8)  * LDO + col];
            float2 p2 = *(const float2*)&sO[(r0 + 16) * LDO + col];
            float2 p3 = *(const float2*)&sO[(r0 + 24) * LDO + col];
            float2 x0 = *(const float2*)&x[(rg)      * CC + col];
            float2 x1 = *(const float2*)&x[(rg + 8)  * CC + col];
            float2 x2 = *(const float2*)&x[(rg + 16) * CC + col];
            float2 x3 = *(const float2*)&x[(rg + 24) * CC + col];
            float2 v;
            v.x = (o0[n][0] + p0.x) * inv0 + x0.x;
            v.y = (o0[n][1] + p0.y) * inv0 + x0.y;
            *(float2*)&out[(rg)      * CC + col] = v;
            v.x = (o0[n][2] + p1.x) * inv1 + x1.x;
            v.y = (o0[n][3] + p1.y) * inv1 + x1.y;
            *(float2*)&out[(rg + 8)  * CC + col] = v;
            v.x = (o1[n][0] + p2.x) * inv2 + x2.x;
            v.y = (o1[n][1] + p2.y) * inv2 + x2.y;
            *(float2*)&out[(rg + 16) * CC + col] = v;
            v.x = (o1[n][2] + p3.x) * inv3 + x3.x;
            v.y = (o1[n][3] + p3.y) * inv3 + x3.y;
            *(float2*)&out[(rg + 24) * CC + col] = v;
        }
    }
}

// ---------------------------------------------------------------------------

extern "C" void kernel_launch(void* const* d_in, const int* in_sizes, int n_in,
                              void* d_out, int out_size)
{
    const float* x     = (const float*)d_in[0];
    const float* kf    = (const float*)d_in[1];
    const float* kg    = (const float*)d_in[2];
    const float* kh    = (const float*)d_in[3];
    const float* gamma = (const float*)d_in[4];
    float*       out   = (float*)d_out;

    proj_kernel<<<(BB * NN) / 128, 256>>>(x, kf, kg, kh);
    attn_kernel<<<BB * QT, 128>>>(x, gamma, out);
}

// round 5
// speedup vs baseline: 1.8970x; 1.1256x over previous
#include <cuda_runtime.h>
#include <cuda_bf16.h>
#include <stdint.h>

#define BB 8
#define NN 4096
#define CC 64
#define QD 8
#define BM 64          // query rows per block
#define BN 64          // key tile rows
#define QT (NN / BM)
#define KT (NN / BN)
#define LDH 72         // sH leading dim
#define LDO 72         // epilogue O overlay leading dim (floats)
#define LOG2E 1.4426950408889634f

// Static device scratch for projections.
__device__ __nv_bfloat16 g_f[BB * NN * QD];   // 0.5 MB
__device__ __nv_bfloat16 g_g[BB * NN * QD];   // 0.5 MB (pre-scaled by log2e)
__device__ __nv_bfloat16 g_h[BB * NN * CC];   // 4 MB

// ---------------------------------------------------------------------------
// PTX helpers
// ---------------------------------------------------------------------------
__device__ __forceinline__ void mma_16n8k8(float* c, const uint32_t* a, uint32_t b)
{
    asm volatile(
        "mma.sync.aligned.m16n8k8.row.col.f32.bf16.bf16.f32 "
        "{%0,%1,%2,%3}, {%4,%5}, {%6}, {%0,%1,%2,%3};\n"
        : "+f"(c[0]), "+f"(c[1]), "+f"(c[2]), "+f"(c[3])
        : "r"(a[0]), "r"(a[1]), "r"(b));
}

__device__ __forceinline__ void mma_16n8k16(float* c, const uint32_t* a, const uint32_t* b)
{
    asm volatile(
        "mma.sync.aligned.m16n8k16.row.col.f32.bf16.bf16.f32 "
        "{%0,%1,%2,%3}, {%4,%5,%6,%7}, {%8,%9}, {%0,%1,%2,%3};\n"
        : "+f"(c[0]), "+f"(c[1]), "+f"(c[2]), "+f"(c[3])
        : "r"(a[0]), "r"(a[1]), "r"(a[2]), "r"(a[3]), "r"(b[0]), "r"(b[1]));
}

__device__ __forceinline__ void ldsm_x4(uint32_t* r, const void* smem_ptr)
{
    uint32_t addr = (uint32_t)__cvta_generic_to_shared(smem_ptr);
    asm volatile(
        "ldmatrix.sync.aligned.m8n8.x4.shared.b16 {%0,%1,%2,%3}, [%4];\n"
        : "=r"(r[0]), "=r"(r[1]), "=r"(r[2]), "=r"(r[3]) : "r"(addr));
}

__device__ __forceinline__ void ldsm_x4_trans(uint32_t* r, const void* smem_ptr)
{
    uint32_t addr = (uint32_t)__cvta_generic_to_shared(smem_ptr);
    asm volatile(
        "ldmatrix.sync.aligned.m8n8.x4.trans.shared.b16 {%0,%1,%2,%3}, [%4];\n"
        : "=r"(r[0]), "=r"(r[1]), "=r"(r[2]), "=r"(r[3]) : "r"(addr));
}

__device__ __forceinline__ uint32_t pack_bf162(float a, float b)
{
    __nv_bfloat162 t = __floats2bfloat162_rn(a, b);
    return *(uint32_t*)&t;
}

// cvt two fp32 -> bf16x2 (lo, hi), then exp2 both halves in ONE MUFU op.
__device__ __forceinline__ uint32_t ex2_pair(float lo, float hi)
{
    uint32_t t, y;
    asm("cvt.rn.bf16x2.f32 %0, %1, %2;\n" : "=r"(t) : "f"(hi), "f"(lo));
    asm("ex2.approx.ftz.bf16x2 %0, %1;\n" : "=r"(y) : "r"(t));
    return y;
}

__device__ __forceinline__ void cp_async16(void* smem_dst, const void* gmem_src)
{
    uint32_t d = (uint32_t)__cvta_generic_to_shared(smem_dst);
    asm volatile("cp.async.cg.shared.global [%0], [%1], 16;\n"
                 :: "r"(d), "l"(gmem_src) : "memory");
}
__device__ __forceinline__ void cp_async_commit()
{
    asm volatile("cp.async.commit_group;\n" ::: "memory");
}
__device__ __forceinline__ void cp_async_wait0()
{
    asm volatile("cp.async.wait_group 0;\n" ::: "memory");
}

// ---------------------------------------------------------------------------
// Kernel 1: projections as HMMA GEMM.  [128 rows x 64] @ [64 x 80] per block.
// 256 blocks x 256 threads (8 warps, 16 rows each). Wg pre-scaled by log2e.
// ---------------------------------------------------------------------------
#define LDW 88
#define LDX 72
__global__ __launch_bounds__(256) void proj_kernel(
    const float* __restrict__ x,
    const float* __restrict__ kf,
    const float* __restrict__ kg,
    const float* __restrict__ kh)
{
    __shared__ __nv_bfloat16 sW[64 * LDW];    // row c: d 0-7 f, 8-15 g(scaled), 16-79 h
    __shared__ __nv_bfloat16 sX[128 * LDX];

    int tid  = threadIdx.x;
    int lane = tid & 31;
    int w    = tid >> 5;
    int gid  = lane >> 2;
    int tg   = lane & 3;

    for (int idx = tid; idx < 64 * 80; idx += 256) {
        int c = idx / 80, d = idx % 80;
        float v;
        if (d < 8)       v = kf[c * 8 + d];
        else if (d < 16) v = kg[c * 8 + (d - 8)] * LOG2E;
        else             v = kh[c * 64 + (d - 16)];
        sW[c * LDW + d] = __float2bfloat16(v);
    }
    long base = (long)blockIdx.x * 128;
    const float4* xg = (const float4*)(x + base * 64);
    for (int i = tid; i < 2048; i += 256) {
        int r = i >> 4, c4 = (i & 15) * 4;
        float4 v = xg[i];
        __nv_bfloat162* dst = (__nv_bfloat162*)&sX[r * LDX + c4];
        dst[0] = __floats2bfloat162_rn(v.x, v.y);
        dst[1] = __floats2bfloat162_rn(v.z, v.w);
    }
    __syncthreads();

    float c[10][4];
#pragma unroll
    for (int n = 0; n < 10; n++)
#pragma unroll
        for (int i = 0; i < 4; i++) c[n][i] = 0.f;

#pragma unroll
    for (int kk = 0; kk < 4; kk++) {
        uint32_t a[4];
        ldsm_x4(a, &sX[(w * 16 + (lane & 15)) * LDX + kk * 16 + (lane >> 4) * 8]);
#pragma unroll
        for (int np = 0; np < 5; np++) {
            uint32_t bfr[4];
            ldsm_x4_trans(bfr,
                &sW[(kk * 16 + (lane & 15)) * LDW + np * 16 + (lane >> 4) * 8]);
            mma_16n8k16(c[2 * np],     a, &bfr[0]);
            mma_16n8k16(c[2 * np + 1], a, &bfr[2]);
        }
    }

    // Fragment-direct scattered stores: d = 16*np + 8*h + 2*tg (static routing).
    long r0 = base + w * 16 + gid;
    long r1 = r0 + 8;
#pragma unroll
    for (int np = 0; np < 5; np++) {
#pragma unroll
        for (int h = 0; h < 2; h++) {
            int dbase = 16 * np + 8 * h;
            uint32_t u0 = pack_bf162(c[2 * np + h][0], c[2 * np + h][1]);
            uint32_t u1 = pack_bf162(c[2 * np + h][2], c[2 * np + h][3]);
            if (dbase == 0) {
                *(uint32_t*)&g_f[r0 * QD + 2 * tg] = u0;
                *(uint32_t*)&g_f[r1 * QD + 2 * tg] = u1;
            } else if (dbase == 8) {
                *(uint32_t*)&g_g[r0 * QD + 2 * tg] = u0;
                *(uint32_t*)&g_g[r1 * QD + 2 * tg] = u1;
            } else {
                int d = dbase - 16 + 2 * tg;
                *(uint32_t*)&g_h[r0 * CC + d] = u0;
                *(uint32_t*)&g_h[r1 * CC + d] = u1;
            }
        }
    }
}

// ---------------------------------------------------------------------------
// Kernel 2: flash attention. 128 threads = 2 warp-pairs (key-tile parity
// split). Warp-in-pair wp covers rows [wp*32, wp*32+32) as two m16 chunks
// sharing every H B-fragment. Softmax row-sums accumulated by the TENSOR
// CORE via a constant ones-column B fragment; exps via bf16x2 ex2 (2/MUFU op).
// ---------------------------------------------------------------------------
__global__ __launch_bounds__(128) void attn_kernel(
    const float* __restrict__ x,
    const float* __restrict__ gamma_p,
    float* __restrict__ out)
{
    __shared__ __nv_bfloat16 sG[BM * QD];             // 1 KB
    __shared__ __nv_bfloat16 sF[2][2][BN * QD];       // 4 KB   [pair][buf]
    __shared__ __nv_bfloat16 sH[2][2][BN * LDH];      // 36 KB  [pair][buf]
    __shared__ float         sL[BM];

    int tid  = threadIdx.x;
    int lane = tid & 31;
    int w    = tid >> 5;          // 0..3
    int pair = w >> 1;            // key-tile parity this warp handles
    int wp   = w & 1;             // warp-in-pair: row half
    int pt   = tid & 63;          // pair-local thread id
    int gid  = lane >> 2;
    int tg   = lane & 3;
    int b    = blockIdx.x / QT;
    int qt   = blockIdx.x % QT;
    long qbase = (long)b * NN + (long)qt * BM;
    long kb0   = (long)b * NN;

    float gmm = gamma_p[0];

    // Ones B-fragment for rowsum MMA: column n=0 of B[k,n] = 1.0 (bf16).
    uint32_t one2 = (lane < 4) ? 0x3F803F80u : 0u;
    uint32_t bones[2] = { one2, one2 };

    // Prologue: G tile + each pair's first key tile (kt = pair).
    if (tid < 64) cp_async16(&sG[tid * 8], &g_g[(qbase + tid) * QD]);
    {
        long kb = kb0 + (long)pair * BN;
        cp_async16(&sF[pair][0][pt * 8], &g_f[(kb + pt) * QD]);
#pragma unroll
        for (int i = 0; i < 8; i++) {
            int idx = pt + 64 * i;
            cp_async16(&sH[pair][0][(idx >> 3) * LDH + (idx & 7) * 8],
                       &g_h[kb * CC + idx * 8]);
        }
    }
    cp_async_commit();
    cp_async_wait0();
    __syncthreads();

    // G A-fragments for rows wp*32 + {gid, gid+8, gid+16, gid+24}.
    uint32_t ga0[2], ga1[2];
    ga0[0] = *(const uint32_t*)&sG[(wp * 32 + gid)      * QD + 2 * tg];
    ga0[1] = *(const uint32_t*)&sG[(wp * 32 + gid + 8)  * QD + 2 * tg];
    ga1[0] = *(const uint32_t*)&sG[(wp * 32 + gid + 16) * QD + 2 * tg];
    ga1[1] = *(const uint32_t*)&sG[(wp * 32 + gid + 24) * QD + 2 * tg];

    float o0[8][4], o1[8][4];
#pragma unroll
    for (int n = 0; n < 8; n++)
#pragma unroll
        for (int i = 0; i < 4; i++) { o0[n][i] = 0.f; o1[n][i] = 0.f; }
    float lacc0[4] = {0.f, 0.f, 0.f, 0.f};
    float lacc1[4] = {0.f, 0.f, 0.f, 0.f};

    const int NI = KT / 2;   // 32 iterations per pair
    for (int i = 0; i < NI; i++) {
        int buf = i & 1;
        const __nv_bfloat16* hb = &sH[pair][buf][0];

        // Prefetch this pair's next key tile (kt = 2*(i+1)+pair).
        if (i + 1 < NI) {
            long kb = kb0 + (long)(2 * (i + 1) + pair) * BN;
            cp_async16(&sF[pair][buf ^ 1][pt * 8], &g_f[(kb + pt) * QD]);
#pragma unroll
            for (int j = 0; j < 8; j++) {
                int idx = pt + 64 * j;
                cp_async16(&sH[pair][buf ^ 1][(idx >> 3) * LDH + (idx & 7) * 8],
                           &g_h[kb * CC + idx * 8]);
            }
            cp_async_commit();
        }

        // F B-fragments (single LDS.32 each).
        uint32_t fb[8];
#pragma unroll
        for (int j = 0; j < 8; j++)
            fb[j] = *(const uint32_t*)&sF[pair][buf][(j * 8 + gid) * QD + 2 * tg];

        // Per 16-key slab: S-MMA -> bf16x2 exp -> rowsum-MMA + PV-MMA.
#pragma unroll
        for (int kk = 0; kk < 4; kk++) {
            float s00[4] = {0.f,0.f,0.f,0.f}, s01[4] = {0.f,0.f,0.f,0.f};
            float s10[4] = {0.f,0.f,0.f,0.f}, s11[4] = {0.f,0.f,0.f,0.f};
            mma_16n8k8(s00, ga0, fb[2 * kk]);
            mma_16n8k8(s01, ga0, fb[2 * kk + 1]);
            mma_16n8k8(s10, ga1, fb[2 * kk]);
            mma_16n8k8(s11, ga1, fb[2 * kk + 1]);

            uint32_t a0[4], a1[4];
            a0[0] = ex2_pair(s00[0], s00[1]);
            a0[1] = ex2_pair(s00[2], s00[3]);
            a0[2] = ex2_pair(s01[0], s01[1]);
            a0[3] = ex2_pair(s01[2], s01[3]);
            a1[0] = ex2_pair(s10[0], s10[1]);
            a1[1] = ex2_pair(s10[2], s10[3]);
            a1[2] = ex2_pair(s11[0], s11[1]);
            a1[3] = ex2_pair(s11[2], s11[3]);

            // Row-sums on the tensor pipe (exact sum of the rounded P).
            mma_16n8k16(lacc0, a0, bones);
            mma_16n8k16(lacc1, a1, bones);

#pragma unroll
            for (int np = 0; np < 4; np++) {
                uint32_t bfr[4];
                ldsm_x4_trans(bfr,
                    &hb[(kk * 16 + (lane & 15)) * LDH + np * 16 + (lane >> 4) * 8]);
                mma_16n8k16(o0[2 * np],     a0, &bfr[0]);
                mma_16n8k16(o0[2 * np + 1], a0, &bfr[2]);
                mma_16n8k16(o1[2 * np],     a1, &bfr[0]);
                mma_16n8k16(o1[2 * np + 1], a1, &bfr[2]);
            }
        }

        if (i + 1 < NI) {
            cp_async_wait0();
            asm volatile("bar.sync %0, 64;\n" :: "r"(1 + pair) : "memory");
        }
    }

    // Row-sums live in column 0 of lacc (lanes with tg==0). Broadcast to the
    // 4 lanes of each row group.
    int src = lane & 28;
    float l0 = __shfl_sync(0xffffffffu, lacc0[0], src);
    float l1 = __shfl_sync(0xffffffffu, lacc0[2], src);
    float l2 = __shfl_sync(0xffffffffu, lacc1[0], src);
    float l3 = __shfl_sync(0xffffffffu, lacc1[2], src);

    // Join the two pairs: pair 1 parks partial O + l in smem (overlaying the
    // dead sH buffers), pair 0 combines and writes out.
    __syncthreads();
    float* sO = (float*)&sH[0][0][0];   // 64 x LDO floats (< 36 KB)
    int r0 = wp * 32 + gid;
    if (pair == 1) {
#pragma unroll
        for (int n = 0; n < 8; n++) {
            int col = n * 8 + 2 * tg;
            *(float2*)&sO[(r0)      * LDO + col] = make_float2(o0[n][0], o0[n][1]);
            *(float2*)&sO[(r0 + 8)  * LDO + col] = make_float2(o0[n][2], o0[n][3]);
            *(float2*)&sO[(r0 + 16) * LDO + col] = make_float2(o1[n][0], o1[n][1]);
            *(float2*)&sO[(r0 + 24) * LDO + col] = make_float2(o1[n][2], o1[n][3]);
        }
        if (tg == 0) {
            sL[r0] = l0; sL[r0 + 8] = l1; sL[r0 + 16] = l2; sL[r0 + 24] = l3;
        }
    }
    __syncthreads();
    if (pair == 0) {
        float inv0 = gmm / (l0 + sL[r0]);
        float inv1 = gmm / (l1 + sL[r0 + 8]);
        float inv2 = gmm / (l2 + sL[r0 + 16]);
        float inv3 = gmm / (l3 + sL[r0 + 24]);
        long rg = qbase + r0;
#pragma unroll
        for (int n = 0; n < 8; n++) {
            int col = n * 8 + 2 * tg;
            float2 p0 = *(const float2*)&sO[(r0)      * LDO + col];
            float2 p1 = *(const float2*)&sO[(r0 + 8)  * LDO + col];
            float2 p2 = *(const float2*)&sO[(r0 + 16) * LDO + col];
            float2 p3 = *(const float2*)&sO[(r0 + 24) * LDO + col];
            float2 x0 = *(const float2*)&x[(rg)      * CC + col];
            float2 x1 = *(const float2*)&x[(rg + 8)  * CC + col];
            float2 x2 = *(const float2*)&x[(rg + 16) * CC + col];
            float2 x3 = *(const float2*)&x[(rg + 24) * CC + col];
            float2 v;
            v.x = (o0[n][0] + p0.x) * inv0 + x0.x;
            v.y = (o0[n][1] + p0.y) * inv0 + x0.y;
            *(float2*)&out[(rg)      * CC + col] = v;
            v.x = (o0[n][2] + p1.x) * inv1 + x1.x;
            v.y = (o0[n][3] + p1.y) * inv1 + x1.y;
            *(float2*)&out[(rg + 8)  * CC + col] = v;
            v.x = (o1[n][0] + p2.x) * inv2 + x2.x;
            v.y = (o1[n][1] + p2.y) * inv2 + x2.y;
            *(float2*)&out[(rg + 16) * CC + col] = v;
            v.x = (o1[n][2] + p3.x) * inv3 + x3.x;
            v.y = (o1[n][3] + p3.y) * inv3 + x3.y;
            *(float2*)&out[(rg + 24) * CC + col] = v;
        }
    }
}

// ---------------------------------------------------------------------------

extern "C" void kernel_launch(void* const* d_in, const int* in_sizes, int n_in,
                              void* d_out, int out_size)
{
    const float* x     = (const float*)d_in[0];
    const float* kf    = (const float*)d_in[1];
    const float* kg    = (const float*)d_in[2];
    const float* kh    = (const float*)d_in[3];
    const float* gamma = (const float*)d_in[4];
    float*       out   = (float*)d_out;

    proj_kernel<<<(BB * NN) / 128, 256>>>(x, kf, kg, kh);
    attn_kernel<<<BB * QT, 128>>>(x, gamma, out);
}